// round 1
// baseline (speedup 1.0000x reference)
#include <cuda_runtime.h>

#define B_  4
#define H_  256
#define W_  256
#define CIN 256
#define CM  64
#define HW  (H_*W_)

// ---------------- scratch (static device memory — no allocations) ----------------
__device__ float g_y[(size_t)B_*CM*HW];       // 64 MB: conv_in output
__device__ float g_edge[(size_t)B_*CM*HW];    // 64 MB: edge_raw (pre-normalization)
__device__ float g_wT[CIN*CM];                // w_in transposed [c][o]
__device__ float g_weffT[B_*CM*CM];           // folded output weights [b][c][o]
__device__ float g_sums[B_*CM];               // per-(b,c) edge sums
__device__ unsigned int g_maxbits;            // global max (float bits, edge>=0)

// Separable gaussian taps (sigma=2, size=5), matching reference normalization
static constexpr double GE0 = 0.6065306597126334;   // exp(-0.5)
static constexpr double GE1 = 0.8824969025845955;   // exp(-0.125)
static constexpr double GSUM = 2.0*(GE0+GE1)+1.0;
static constexpr float G0 = (float)(GE0/GSUM);
static constexpr float G1 = (float)(GE1/GSUM);
static constexpr float G2 = (float)(1.0/GSUM);

// ---------------- init: transpose w_in, zero reductions ----------------
__global__ void k_init(const float* __restrict__ w_in) {
    int i = blockIdx.x*256 + threadIdx.x;
    if (i < CIN*CM) {
        int c = i >> 6, o = i & 63;
        g_wT[i] = w_in[o*CIN + c];
    }
    if (i < B_*CM) g_sums[i] = 0.f;
    if (i == 0) g_maxbits = 0u;
}

// ---------------- conv1x1 in: [B,256,H,W] -> [B,64,H,W] ----------------
// Block = one (b,h) row of 256 pixels. 256 threads: 8 out-groups x 32 px-groups.
// Thread tile: 8 outputs x 8 pixels = 64 fp32 accumulators.
__global__ __launch_bounds__(256)
void k_conv_in(const float* __restrict__ x, const float* __restrict__ b_in) {
    const int t  = threadIdx.x;
    const int pg = t & 31, og = t >> 5;
    const int bx = blockIdx.x;
    const int b  = bx >> 8, h = bx & 255;
    const float* __restrict__ xrow = x + (size_t)b*CIN*HW + h*W_ + pg*8;
    const float* __restrict__ wp   = g_wT + og*8;

    float acc[8][8];
#pragma unroll
    for (int o = 0; o < 8; ++o)
#pragma unroll
        for (int p = 0; p < 8; ++p) acc[o][p] = 0.f;

#pragma unroll 4
    for (int c = 0; c < CIN; ++c) {
        float4 xa = *(const float4*)(xrow + (size_t)c*HW);
        float4 xb = *(const float4*)(xrow + (size_t)c*HW + 4);
        float4 wa = *(const float4*)(wp + c*CM);
        float4 wb = *(const float4*)(wp + c*CM + 4);
        float xv[8] = {xa.x,xa.y,xa.z,xa.w,xb.x,xb.y,xb.z,xb.w};
        float wv[8] = {wa.x,wa.y,wa.z,wa.w,wb.x,wb.y,wb.z,wb.w};
#pragma unroll
        for (int o = 0; o < 8; ++o)
#pragma unroll
            for (int p = 0; p < 8; ++p)
                acc[o][p] = fmaf(wv[o], xv[p], acc[o][p]);
    }

#pragma unroll
    for (int o = 0; o < 8; ++o) {
        int oo = og*8 + o;
        float bias = b_in[oo];
        float* yo = g_y + (size_t)(b*CM + oo)*HW + h*W_ + pg*8;
        float4 r0 = make_float4(acc[o][0]+bias, acc[o][1]+bias, acc[o][2]+bias, acc[o][3]+bias);
        float4 r1 = make_float4(acc[o][4]+bias, acc[o][5]+bias, acc[o][6]+bias, acc[o][7]+bias);
        *(float4*)yo       = r0;
        *(float4*)(yo + 4) = r1;
    }
}

// ---------------- fused gaussian(separable) + scharr/laplacian + reductions ----------------
#define TW 64
#define TH 32
__global__ __launch_bounds__(256)
void k_edge() {
    __shared__ float ysh[TH+6][TW+8];    // input tile + halo 3 (zero-padded)
    __shared__ float tsh[TH+6][TW+4];    // horizontal gaussian
    __shared__ float smsh[TH+2][TW+4];   // blurred, + halo 1 (zero outside image)

    const int t  = threadIdx.x;
    const int x0 = blockIdx.x*TW, y0 = blockIdx.y*TH;
    const int bc = blockIdx.z;
    const float* __restrict__ yp = g_y   + (size_t)bc*HW;
    float* __restrict__       ep = g_edge + (size_t)bc*HW;

    // load y tile with halo 3 (zero padding)
    for (int i = t; i < (TH+6)*(TW+6); i += 256) {
        int rr = i/(TW+6), cc = i - rr*(TW+6);
        int gr = y0 - 3 + rr, gc = x0 - 3 + cc;
        float v = 0.f;
        if ((unsigned)gr < H_ && (unsigned)gc < W_) v = yp[gr*W_ + gc];
        ysh[rr][cc] = v;
    }
    __syncthreads();

    // horizontal gaussian: cols [x0-1 .. x0+64]
    for (int i = t; i < (TH+6)*(TW+2); i += 256) {
        int rr = i/(TW+2), jj = i - rr*(TW+2);
        tsh[rr][jj] = G0*(ysh[rr][jj] + ysh[rr][jj+4])
                    + G1*(ysh[rr][jj+1] + ysh[rr][jj+3])
                    + G2* ysh[rr][jj+2];
    }
    __syncthreads();

    // vertical gaussian: rows [y0-1 .. y0+32]; zero outside image (3x3 zero-pad)
    for (int i = t; i < (TH+2)*(TW+2); i += 256) {
        int ii = i/(TW+2), jj = i - ii*(TW+2);
        int sr = y0 - 1 + ii, sc = x0 - 1 + jj;
        float v = 0.f;
        if ((unsigned)sr < H_ && (unsigned)sc < W_)
            v = G0*(tsh[ii][jj] + tsh[ii+4][jj])
              + G1*(tsh[ii+1][jj] + tsh[ii+3][jj])
              + G2* tsh[ii+2][jj];
        smsh[ii][jj] = v;
    }
    __syncthreads();

    // scharr + laplacian (cross-correlation, matching lax.conv) + edge magnitude
    float lsum = 0.f, lmax = 0.f;
    for (int i = t; i < TH*TW; i += 256) {
        int ty = i >> 6, tx = i & 63;
        float a  = smsh[ty  ][tx], bb = smsh[ty  ][tx+1], c2 = smsh[ty  ][tx+2];
        float d  = smsh[ty+1][tx], e  = smsh[ty+1][tx+1], f  = smsh[ty+1][tx+2];
        float g  = smsh[ty+2][tx], h2 = smsh[ty+2][tx+1], i2 = smsh[ty+2][tx+2];
        float g0v  = 3.f*(a - c2) + 10.f*(d  - f ) + 3.f*(g  - i2);
        float g90v = 3.f*(a - g ) + 10.f*(bb - h2) + 3.f*(c2 - i2);
        float lap  = 4.f*e - bb - d - f - h2;
        float edge = fmaxf(fabsf(g0v), fabsf(g90v)) + 0.1f*fabsf(lap);
        ep[(y0+ty)*W_ + x0 + tx] = edge;
        lsum += edge;
        lmax = fmaxf(lmax, edge);
    }

    // block reduce sum & max
#pragma unroll
    for (int off = 16; off; off >>= 1) {
        lsum += __shfl_down_sync(0xffffffffu, lsum, off);
        lmax  = fmaxf(lmax, __shfl_down_sync(0xffffffffu, lmax, off));
    }
    __shared__ float rs[8], rm[8];
    int wid = t >> 5, lane = t & 31;
    if (lane == 0) { rs[wid] = lsum; rm[wid] = lmax; }
    __syncthreads();
    if (t == 0) {
        float s = 0.f, m = 0.f;
#pragma unroll
        for (int wI = 0; wI < 8; ++wI) { s += rs[wI]; m = fmaxf(m, rm[wI]); }
        atomicAdd(&g_sums[bc], s);
        atomicMax(&g_maxbits, __float_as_uint(m));  // edge >= 0: uint order == float order
    }
}

// ---------------- SE MLP + fold scale/max into output weights ----------------
// clip(edge/(max+eps),0,1) is identity since 0 <= edge <= max, so
// pooled = sums / (HW * (max+eps)); w_effT[b][c][o] = w_out[o][c]*scale[b][c]/(max+eps)
__global__ void k_se(const float* __restrict__ w_fc1, const float* __restrict__ b_fc1,
                     const float* __restrict__ w_fc2, const float* __restrict__ b_fc2,
                     const float* __restrict__ w_out) {
    __shared__ float pooled[B_][CM];
    __shared__ float hsh[B_][4];
    __shared__ float ssh[B_][CM];
    __shared__ float inv_s;
    int t = threadIdx.x;
    if (t == 0) inv_s = 1.f/(__uint_as_float(g_maxbits) + 1e-8f);
    __syncthreads();
    float inv = inv_s;
    if (t < B_*CM)
        pooled[t>>6][t&63] = g_sums[t] * inv * (1.f/(float)HW);
    __syncthreads();
    if (t < B_*4) {
        int b = t >> 2, j = t & 3;
        float z = b_fc1[j];
        for (int c = 0; c < CM; ++c) z += w_fc1[j*CM + c]*pooled[b][c];
        hsh[b][j] = fmaxf(z, 0.f);
    }
    __syncthreads();
    if (t < B_*CM) {
        int b = t >> 6, c = t & 63;
        float z = b_fc2[c];
#pragma unroll
        for (int j = 0; j < 4; ++j) z += w_fc2[c*4 + j]*hsh[b][j];
        ssh[b][c] = 1.f/(1.f + expf(-z));
    }
    __syncthreads();
    for (int i = t; i < B_*CM*CM; i += 256) {
        int b = i >> 12, rem = i & 4095, c = rem >> 6, o = rem & 63;
        g_weffT[i] = w_out[o*CM + c] * ssh[b][c] * inv;
    }
}

// ---------------- conv1x1 out: [B,64,H,W] -> [B,64,H,W] with per-b folded weights ----------------
__global__ __launch_bounds__(256)
void k_conv_out(const float* __restrict__ b_out, float* __restrict__ out) {
    const int t  = threadIdx.x;
    const int pg = t & 31, og = t >> 5;
    const int bx = blockIdx.x;
    const int b  = bx >> 8, h = bx & 255;
    const float* __restrict__ erow = g_edge + (size_t)b*CM*HW + h*W_ + pg*8;
    const float* __restrict__ wp   = g_weffT + b*CM*CM + og*8;

    float acc[8][8];
#pragma unroll
    for (int o = 0; o < 8; ++o)
#pragma unroll
        for (int p = 0; p < 8; ++p) acc[o][p] = 0.f;

#pragma unroll 4
    for (int c = 0; c < CM; ++c) {
        float4 xa = *(const float4*)(erow + (size_t)c*HW);
        float4 xb = *(const float4*)(erow + (size_t)c*HW + 4);
        float4 wa = *(const float4*)(wp + c*CM);
        float4 wb = *(const float4*)(wp + c*CM + 4);
        float xv[8] = {xa.x,xa.y,xa.z,xa.w,xb.x,xb.y,xb.z,xb.w};
        float wv[8] = {wa.x,wa.y,wa.z,wa.w,wb.x,wb.y,wb.z,wb.w};
#pragma unroll
        for (int o = 0; o < 8; ++o)
#pragma unroll
            for (int p = 0; p < 8; ++p)
                acc[o][p] = fmaf(wv[o], xv[p], acc[o][p]);
    }

#pragma unroll
    for (int o = 0; o < 8; ++o) {
        int oo = og*8 + o;
        float bias = b_out[oo];
        float* po = out + (size_t)(b*CM + oo)*HW + h*W_ + pg*8;
        float4 r0 = make_float4(acc[o][0]+bias, acc[o][1]+bias, acc[o][2]+bias, acc[o][3]+bias);
        float4 r1 = make_float4(acc[o][4]+bias, acc[o][5]+bias, acc[o][6]+bias, acc[o][7]+bias);
        *(float4*)po       = r0;
        *(float4*)(po + 4) = r1;
    }
}

// ---------------- launch ----------------
extern "C" void kernel_launch(void* const* d_in, const int* in_sizes, int n_in,
                              void* d_out, int out_size) {
    const float* x     = (const float*)d_in[0];
    const float* w_in  = (const float*)d_in[1];
    const float* b_in  = (const float*)d_in[2];
    const float* w_fc1 = (const float*)d_in[3];
    const float* b_fc1 = (const float*)d_in[4];
    const float* w_fc2 = (const float*)d_in[5];
    const float* b_fc2 = (const float*)d_in[6];
    const float* w_out = (const float*)d_in[7];
    const float* b_out = (const float*)d_in[8];
    float* out = (float*)d_out;

    k_init<<<64, 256>>>(w_in);
    k_conv_in<<<B_*H_, 256>>>(x, b_in);
    k_edge<<<dim3(W_/TW, H_/TH, B_*CM), 256>>>();
    k_se<<<1, 256>>>(w_fc1, b_fc1, w_fc2, b_fc2, w_out);
    k_conv_out<<<B_*H_, 256>>>(b_out, out);
}